// round 13
// baseline (speedup 1.0000x reference)
#include <cuda_runtime.h>
#include <cuda_bf16.h>
#include <math.h>

#define Bn 4096
#define Kn 3000
#define KP 3072            /* padded row stride (bf16 elems)          */
#define NBB 148            /* persistent blocks (512 thr, 2 halves)   */
#define NT 256             /* threads per half                        */
#define RO 16              /* SMEM-owned rows per slot per block      */
#define OWNED (NBB * RO)   /* 2368 rows resident in SMEM per slot     */
#define NSTM 12            /* max streamed rows per block per slot    */
#define DSMEM (2 * RO * KP * 2 + 2 * KP * 4)   /* 221184 B */

#define TINYF 1e-12f
#define TOLF  1e-3f
#define INV_EPS 20.0f      /* 1/0.05 */
#define INV_TEMP 10.0f     /* 1/0.1  */
#define TC 1.3653333333333333f   /* 4096/3000 */

static __device__ __align__(16) __nv_bfloat16 g_Qh[2][(size_t)Bn * KP]; // ~50 MB
static __device__ __align__(16) float g_tpart[2][2][(size_t)NBB * KP];  // 7.3 MB
static __device__ __align__(16) float g_v[2][KP];
static __device__ __align__(16) float g_beta[2][Kn];
static __device__ float    g_alpha[2][Bn];
static __device__ unsigned g_rowerr[2][104];
static __device__ unsigned g_colerr[2][104];
static __device__ float    g_ent[2];
static __device__ float    g_qmax[2];
static __device__ float    g_loss;
static __device__ unsigned g_bar_count;
static __device__ unsigned g_bar_gen;

struct Ptrs { const float* p[8]; };

// ---------------- grid barrier (148 resident blocks) ------------------------
static __device__ __forceinline__ void grid_sync()
{
    __syncthreads();
    if (threadIdx.x == 0) {
        volatile unsigned* vgen = &g_bar_gen;
        unsigned gen = *vgen;
        __threadfence();
        unsigned t = atomicAdd(&g_bar_count, 1u);
        if (t == (unsigned)NBB - 1u) {
            g_bar_count = 0u;
            __threadfence();
            *vgen = gen + 1u;
        } else {
            while (*vgen == gen) { __nanosleep(20); }
        }
        __threadfence();
    }
    __syncthreads();
}

// ---------------- init ------------------------------------------------------
__global__ void init_kernel()
{
    if (threadIdx.x == 0) {
        g_loss = 0.f;
        g_ent[0] = g_ent[1] = 0.f;
        g_qmax[0] = g_qmax[1] = 0.f;
        g_bar_count = 0u;
    }
}

// ---------------- prep: Qh = bf16(exp(S - rowmax)), padded, vectorized ------
__global__ __launch_bounds__(NT) void prep_kernel(Ptrs ptrs, const int* pia, const int* pib)
{
    __shared__ float wmax[8];
    int b = blockIdx.x & (Bn - 1);
    int s = blockIdx.x >> 12;
    int id = (s == 0) ? *pia : *pib;
    const float4* lg4 = (const float4*)(ptrs.p[id] + (size_t)b * Kn);
    int tid = threadIdx.x, lane = tid & 31, wid = tid >> 5;

    float mx = -3.4e38f;
    for (int i = tid; i < Kn / 4; i += NT) {
        float4 x = lg4[i];
        mx = fmaxf(mx, fmaxf(fmaxf(x.x, x.y), fmaxf(x.z, x.w)));
    }
    #pragma unroll
    for (int o = 16; o; o >>= 1) mx = fmaxf(mx, __shfl_xor_sync(0xffffffffu, mx, o));
    if (lane == 0) wmax[wid] = mx;
    __syncthreads();
    float bm = wmax[0];
    #pragma unroll
    for (int w = 1; w < 8; ++w) bm = fmaxf(bm, wmax[w]);
    float m = bm * INV_EPS;

    uint2* qh = (uint2*)(g_Qh[s] + (size_t)b * KP);
    for (int i = tid; i < KP / 4; i += NT) {
        uint2 st;
        if (i < Kn / 4) {
            float4 x = lg4[i];
            __nv_bfloat162 h0 = __floats2bfloat162_rn(__expf(x.x * INV_EPS - m),
                                                      __expf(x.y * INV_EPS - m));
            __nv_bfloat162 h1 = __floats2bfloat162_rn(__expf(x.z * INV_EPS - m),
                                                      __expf(x.w * INV_EPS - m));
            st.x = *(unsigned*)&h0; st.y = *(unsigned*)&h1;
        } else { st.x = 0u; st.y = 0u; }
        qh[i] = st;
    }
}

// ---------------- helpers ---------------------------------------------------
static __device__ __forceinline__ float row_dot(const __nv_bfloat16* qrow,
                                                const float4* s4, int lane)
{
    const uint4* qr = (const uint4*)qrow;
    float acc = 0.f;
    #pragma unroll
    for (int j = 0; j < 12; ++j) {
        int idx = j * 32 + lane;
        uint4 q = qr[idx];
        float4 sa = s4[idx * 2], sb = s4[idx * 2 + 1];
        float2 f0 = __bfloat1622float2(*reinterpret_cast<__nv_bfloat162*>(&q.x));
        float2 f1 = __bfloat1622float2(*reinterpret_cast<__nv_bfloat162*>(&q.y));
        float2 f2 = __bfloat1622float2(*reinterpret_cast<__nv_bfloat162*>(&q.z));
        float2 f3 = __bfloat1622float2(*reinterpret_cast<__nv_bfloat162*>(&q.w));
        acc += f0.x * sa.x + f0.y * sa.y + f1.x * sa.z + f1.y * sa.w
             + f2.x * sb.x + f2.y * sb.y + f3.x * sb.z + f3.y * sb.w;
    }
    return acc;
}

// col partial over block-owned rows: dst[X*KP + k] = sum_b scal[b] Q[b,k]
// 12 cols/thread (6 bf162 pairs, pair index wtid+256j). No internal syncs.
static __device__ __forceinline__ void col_accum(const __nv_bfloat16* qsh,
                                                 const __nv_bfloat16* Qg,
                                                 int X, int nst, const float* uu,
                                                 float* dst, int wtid)
{
    float a[12];
    #pragma unroll
    for (int e = 0; e < 12; ++e) a[e] = 0.f;

    const unsigned* rp = (const unsigned*)qsh + wtid;      // bf162 units, smem
    #pragma unroll 4
    for (int r = 0; r < RO; ++r) {
        float u = uu[r];
        #pragma unroll
        for (int j = 0; j < 6; ++j) {
            unsigned qv = rp[(size_t)r * (KP / 2) + 256 * j];
            float2 f = __bfloat1622float2(*(__nv_bfloat162*)&qv);
            a[2 * j] += u * f.x; a[2 * j + 1] += u * f.y;
        }
    }
    for (int s = 0; s < nst; ++s) {
        float u = uu[RO + s];
        const unsigned* gp = (const unsigned*)(Qg + (size_t)(OWNED + X + NBB * s) * KP) + wtid;
        #pragma unroll
        for (int j = 0; j < 6; ++j) {
            unsigned qv = gp[256 * j];
            float2 f = __bfloat1622float2(*(__nv_bfloat162*)&qv);
            a[2 * j] += u * f.x; a[2 * j + 1] += u * f.y;
        }
    }
    float* o = dst + (size_t)X * KP;
    #pragma unroll
    for (int j = 0; j < 6; ++j)
        *(float2*)(o + 2 * (wtid + 256 * j)) = make_float2(a[2 * j], a[2 * j + 1]);
}

// ---------------- fused persistent Sinkhorn (SMEM-resident Q) ---------------
__global__ __launch_bounds__(512, 1) void sinkhorn_fused()
{
    extern __shared__ __align__(16) char dsm[];
    __shared__ float su[2][2][RO + NSTM];   // u by parity, block-local
    __shared__ float sr[2][RO + NSTM];      // final r
    __shared__ float sw1[2][RO + NSTM];
    __shared__ float swr[2][8], sqr[2][8];

    const int tid = threadIdx.x;
    const int wg = tid >> 8, wtid = tid & 255;
    const int lane = tid & 31, wid = wtid >> 5;
    const int slot = wg;
    const int X = blockIdx.x;
    __nv_bfloat16* qsh = (__nv_bfloat16*)dsm + (size_t)wg * RO * KP;
    float* svh = (float*)(dsm + 2 * RO * KP * 2) + wg * KP;
    const __nv_bfloat16* Qg = g_Qh[slot];
    const int nst = (Bn - OWNED - X + NBB - 1) / NBB;   // 11 or 12

    // copy own rows to SMEM (block-local; grid_sync below orders err zeroing)
    {
        const uint4* src = (const uint4*)(Qg + (size_t)X * RO * KP);
        uint4* dst = (uint4*)qsh;
        for (int i = wtid; i < RO * KP / 8; i += NT) dst[i] = src[i];
    }
    if (X == 0 && wtid < 104) { g_rowerr[slot][wtid] = 0u; g_colerr[slot][wtid] = 0u; }
    grid_sync();

    bool done0 = false, done1 = false;
    int nfin0 = 100, nfin1 = 100;

    for (int iter = 1; iter <= 101; ++iter) {
        const int par = iter & 1, pprev = par ^ 1;
        const bool act = wg ? !done1 : !done0;

        // ---- A: v-reduce, 148 chunks -> g_v (+col err). Coalesced. ----
        if (act && iter >= 2 && X < 12) {
            int col = X * NT + wtid;
            float t = 0.f;
            const float* tp = g_tpart[slot][pprev] + col;
            #pragma unroll 8
            for (int c = 0; c < NBB; ++c) t += tp[(size_t)c * KP];
            float v = TC / (t + TINYF);
            g_v[slot][col] = v;
            float ce = (col < Kn) ? fabsf(v * t - TC) : 0.f;  // all lanes exec shuffle
            #pragma unroll
            for (int o = 16; o; o >>= 1)
                ce = fmaxf(ce, __shfl_xor_sync(0xffffffffu, ce, o));
            if (lane == 0 && ce > 0.f)
                atomicMax(&g_colerr[slot][iter - 1], __float_as_uint(ce));
        }
        grid_sync();

        // ---- B: sv fill + rows (own rows SMEM, streamed rows L2) ----
        if (act) {
            if (iter == 1)
                for (int k = wtid; k < KP; k += NT) svh[k] = (k < Kn) ? 1.f : 0.f;
            else
                for (int k = wtid; k < KP; k += NT) svh[k] = (k < Kn) ? g_v[slot][k] : 0.f;
        }
        __syncthreads();
        if (act) {
            float remax = 0.f;
            const float4* s4 = (const float4*)svh;
            for (int li = wid; li < RO + nst; li += 8) {     // warp-uniform loop
                const __nv_bfloat16* rp = (li < RO)
                    ? qsh + (size_t)li * KP
                    : Qg + (size_t)(OWNED + X + NBB * (li - RO)) * KP;
                float acc = row_dot(rp, s4, lane);
                #pragma unroll
                for (int o = 16; o; o >>= 1)
                    acc += __shfl_xor_sync(0xffffffffu, acc, o);
                float uu = 1.f / (acc + TINYF);
                if (lane == 0) { sr[wg][li] = acc; su[wg][par][li] = uu; }
                if (iter >= 2)
                    remax = fmaxf(remax, fabsf(su[wg][pprev][li] * acc - 1.f));
            }
            if (lane == 0) swr[wg][wid] = remax;
        }
        __syncthreads();
        if (act && wtid == 0 && iter >= 2) {
            float m = swr[wg][0];
            #pragma unroll
            for (int w = 1; w < 8; ++w) m = fmaxf(m, swr[wg][w]);
            if (m > 0.f) atomicMax(&g_rowerr[slot][iter - 1], __float_as_uint(m));
        }

        // ---- C: cols (u block-local, rows->cols is only __syncthreads) ----
        if (act)
            col_accum(qsh, Qg, X, nst, su[wg][par], g_tpart[slot][par], wtid);
        grid_sync();

        // ---- D: convergence (uniform global data) ----
        if (iter >= 2) {
            int it = iter - 1;
            if (!done0) {
                float e = fmaxf(__uint_as_float(g_rowerr[0][it]),
                                __uint_as_float(g_colerr[0][it]));
                if (it >= 3 && (it >= 100 || e <= TOLF)) { done0 = true; nfin0 = it; }
            }
            if (!done1) {
                float e = fmaxf(__uint_as_float(g_rowerr[1][it]),
                                __uint_as_float(g_colerr[1][it]));
                if (it >= 3 && (it >= 100 || e <= TOLF)) { done1 = true; nfin1 = it; }
            }
            if (done0 && done1) break;
        }
    }

    const int nfin = wg ? nfin1 : nfin0;
    const int p = nfin & 1;

    // ---- w1 (block-local) ----
    if (wtid < RO + nst) {
        float u = su[wg][p][wtid], r = sr[wg][wtid];
        sw1[wg][wtid] = u / fmaxf(u * r, TINYF);
    }
    __syncthreads();

    // ---- P1: col sums of row-normalized P -> tpart[1-p] ----
    col_accum(qsh, Qg, X, nst, sw1[wg], g_tpart[slot][1 - p], wtid);
    grid_sync();

    // ---- beta ----
    if (X < 12) {
        int col = X * NT + wtid;
        if (col < Kn) {
            float t = 0.f, cs = 0.f;
            const float* tp = g_tpart[slot][p] + col;
            const float* cp = g_tpart[slot][1 - p] + col;
            #pragma unroll 8
            for (int c = 0; c < NBB; ++c) {
                t  += tp[(size_t)c * KP];
                cs += cp[(size_t)c * KP];
            }
            float v = TC / (t + TINYF);
            float c2 = v * cs;
            g_beta[slot][col] = v * (TC / fmaxf(c2, TINYF));
        }
    }
    grid_sync();

    // ---- P2: alpha, entropy, q_max over block-owned rows ----
    for (int k = wtid; k < KP; k += NT)
        svh[k] = (k < Kn) ? g_beta[slot][k] : 0.f;
    __syncthreads();

    float entacc = 0.f, qsum = 0.f;
    const float4* s4 = (const float4*)svh;
    for (int li = wid; li < RO + nst; li += 8) {
        int grow = (li < RO) ? X * RO + li : OWNED + X + NBB * (li - RO);
        const __nv_bfloat16* rp = (li < RO) ? qsh + (size_t)li * KP
                                            : Qg + (size_t)grow * KP;
        float s2 = row_dot(rp, s4, lane);
        #pragma unroll
        for (int o = 16; o; o >>= 1)
            s2 += __shfl_xor_sync(0xffffffffu, s2, o);
        float w1 = sw1[wg][li];
        float alpha = w1 / fmaxf(w1 * s2, TINYF);
        if (lane == 0) g_alpha[slot][grow] = alpha;

        const uint4* qr = (const uint4*)rp;
        float qm = 0.f;
        #pragma unroll 4
        for (int j = 0; j < 12; ++j) {
            int idx = j * 32 + lane;
            uint4 q = qr[idx];
            float4 sa = s4[idx * 2], sb = s4[idx * 2 + 1];
            float2 f0 = __bfloat1622float2(*reinterpret_cast<__nv_bfloat162*>(&q.x));
            float2 f1 = __bfloat1622float2(*reinterpret_cast<__nv_bfloat162*>(&q.y));
            float2 f2 = __bfloat1622float2(*reinterpret_cast<__nv_bfloat162*>(&q.z));
            float2 f3 = __bfloat1622float2(*reinterpret_cast<__nv_bfloat162*>(&q.w));
            float pe[8] = { f0.x * sa.x, f0.y * sa.y, f1.x * sa.z, f1.y * sa.w,
                            f2.x * sb.x, f2.y * sb.y, f3.x * sb.z, f3.y * sb.w };
            #pragma unroll
            for (int e = 0; e < 8; ++e) {
                float p3 = alpha * pe[e];
                entacc += p3 * __logf(p3 + TINYF);
                qm = fmaxf(qm, p3);
            }
        }
        #pragma unroll
        for (int o = 16; o; o >>= 1)
            qm = fmaxf(qm, __shfl_xor_sync(0xffffffffu, qm, o));
        if (lane == 0) qsum += qm;
    }
    #pragma unroll
    for (int o = 16; o; o >>= 1)
        entacc += __shfl_xor_sync(0xffffffffu, entacc, o);
    __syncthreads();
    if (lane == 0) { swr[wg][wid] = entacc; sqr[wg][wid] = qsum; }
    __syncthreads();
    if (wtid == 0) {
        float e = 0.f, q = 0.f;
        #pragma unroll
        for (int w = 0; w < 8; ++w) { e += swr[wg][w]; q += sqr[wg][w]; }
        atomicAdd(&g_ent[slot], e);
        atomicAdd(&g_qmax[slot], q);
    }
}

// ---------------- loss: single pass, logits registered ----------------------
__global__ __launch_bounds__(NT) void loss_kernel(Ptrs ptrs, const int* pia, const int* pib)
{
    __shared__ __align__(16) float pa[Kn];
    __shared__ __align__(16) float pb[Kn];
    __shared__ float wm[8], wss[8], wda[8], wdb[8];
    int b = blockIdx.x, tid = threadIdx.x;
    int lane = tid & 31, wid = tid >> 5;
    int ia = *pia, ib = *pib;

    float aA = g_alpha[0][b], aB = g_alpha[1][b];
    const uint2* q0 = (const uint2*)(g_Qh[0] + (size_t)b * KP);
    const uint2* q1 = (const uint2*)(g_Qh[1] + (size_t)b * KP);
    const float4* be0 = (const float4*)g_beta[0];
    const float4* be1 = (const float4*)g_beta[1];
    for (int i = tid; i < Kn / 4; i += NT) {
        uint2 v0 = q0[i], v1 = q1[i];
        float4 b0 = be0[i], b1 = be1[i];
        float2 f00 = __bfloat1622float2(*(__nv_bfloat162*)&v0.x);
        float2 f01 = __bfloat1622float2(*(__nv_bfloat162*)&v0.y);
        float2 f10 = __bfloat1622float2(*(__nv_bfloat162*)&v1.x);
        float2 f11 = __bfloat1622float2(*(__nv_bfloat162*)&v1.y);
        ((float4*)pa)[i] = make_float4(aA * f00.x * b0.x, aA * f00.y * b0.y,
                                       aA * f01.x * b0.z, aA * f01.y * b0.w);
        ((float4*)pb)[i] = make_float4(aB * f10.x * b1.x, aB * f10.y * b1.y,
                                       aB * f11.x * b1.z, aB * f11.y * b1.w);
    }
    __syncthreads();

    float accLoss = 0.f;
    for (int c = 0; c < 8; ++c) {
        const float4* lr4 = (const float4*)(ptrs.p[c] + (size_t)b * Kn);
        float4 xv[3];
        float m = -3.4e38f;
        #pragma unroll
        for (int j = 0; j < 3; ++j) {
            int idx = tid + 256 * j;
            if (idx < Kn / 4) {
                xv[j] = lr4[idx];
                m = fmaxf(m, fmaxf(fmaxf(xv[j].x, xv[j].y), fmaxf(xv[j].z, xv[j].w)));
            }
        }
        float s = 0.f, da = 0.f, db = 0.f;
        #pragma unroll
        for (int j = 0; j < 3; ++j) {
            int idx = tid + 256 * j;
            if (idx < Kn / 4) {
                float4 x = xv[j];
                s += __expf(INV_TEMP * (x.x - m)) + __expf(INV_TEMP * (x.y - m))
                   + __expf(INV_TEMP * (x.z - m)) + __expf(INV_TEMP * (x.w - m));
                float4 A = ((const float4*)pa)[idx];
                float4 B = ((const float4*)pb)[idx];
                da += A.x * x.x + A.y * x.y + A.z * x.z + A.w * x.w;
                db += B.x * x.x + B.y * x.y + B.z * x.z + B.w * x.w;
            }
        }
        // exact (m,s) softmax-combine across warp + plain sums
        #pragma unroll
        for (int o = 16; o; o >>= 1) {
            float m2 = __shfl_xor_sync(0xffffffffu, m, o);
            float s2 = __shfl_xor_sync(0xffffffffu, s, o);
            float M = fmaxf(m, m2);
            s = s * __expf(INV_TEMP * (m - M)) + s2 * __expf(INV_TEMP * (m2 - M));
            m = M;
            da += __shfl_xor_sync(0xffffffffu, da, o);
            db += __shfl_xor_sync(0xffffffffu, db, o);
        }
        if (lane == 0) { wm[wid] = m; wss[wid] = s; wda[wid] = da; wdb[wid] = db; }
        __syncthreads();
        if (tid == 0) {
            float M = wm[0];
            #pragma unroll
            for (int w = 1; w < 8; ++w) M = fmaxf(M, wm[w]);
            float S = 0.f, DA = 0.f, DB = 0.f;
            #pragma unroll
            for (int w = 0; w < 8; ++w) {
                S += wss[w] * __expf(INV_TEMP * (wm[w] - M));
                DA += wda[w]; DB += wdb[w];
            }
            float lse = INV_TEMP * M + __logf(S);
            if (c != ia) accLoss += INV_TEMP * DA - lse;
            if (c != ib) accLoss += INV_TEMP * DB - lse;
        }
        __syncthreads();
    }
    if (tid == 0) atomicAdd(&g_loss, accLoss);
}

// ---------------- finalize --------------------------------------------------
__global__ void finalize_kernel(float* out, int out_size)
{
    if (threadIdx.x == 0) {
        float loss = -g_loss / (14.f * (float)Bn);
        float ent  = -0.5f * (g_ent[0] + g_ent[1]) / (float)Bn;
        float qm   =  0.5f * (g_qmax[0] + g_qmax[1]) / (float)Bn;
        if (out_size > 0) out[0] = loss;
        if (out_size > 1) out[1] = ent;
        if (out_size > 2) out[2] = qm;
    }
}

// ---------------- launcher --------------------------------------------------
extern "C" void kernel_launch(void* const* d_in, const int* in_sizes, int n_in,
                              void* d_out, int out_size)
{
    (void)in_sizes; (void)n_in;
    Ptrs ptrs;
    for (int i = 0; i < 8; ++i) ptrs.p[i] = (const float*)d_in[i];
    const int* ia = (const int*)d_in[8];
    const int* ib = (const int*)d_in[9];

    cudaFuncSetAttribute(sinkhorn_fused,
                         cudaFuncAttributeMaxDynamicSharedMemorySize, DSMEM);

    init_kernel<<<1, 32>>>();
    prep_kernel<<<2 * Bn, NT>>>(ptrs, ia, ib);
    sinkhorn_fused<<<NBB, 512, DSMEM>>>();
    loss_kernel<<<Bn, NT>>>(ptrs, ia, ib);
    finalize_kernel<<<1, 32>>>((float*)d_out, out_size);
}